// round 1
// baseline (speedup 1.0000x reference)
#include <cuda_runtime.h>
#include <math.h>

#define Nn 8192
#define Mm 2048
#define Dd 768
// eps = blur^p = 0.05^2
#define EPS_D 0.0025

// -------- scratch (no allocations allowed; static device globals) --------
static __device__ float g_X[(size_t)Nn * Dd];     // x = d @ W^T
static __device__ float g_Y[(size_t)Mm * Dd];     // y = si @ W^T
static __device__ float g_SC[(size_t)Nn * Mm];    // C_xy / eps
static __device__ float g_SCT[(size_t)Mm * Nn];   // transpose
static __device__ float g_nx[Nn];                 // 0.5*|x_i|^2
static __device__ float g_ny[Mm];                 // 0.5*|y_j|^2
static __device__ float g_la[Nn];                 // log h
static __device__ float g_lb[Mm];                 // log hi
static __device__ float g_va[Nn];                 // la + f/eps
static __device__ float g_vb[Mm];                 // lb + g/eps
static __device__ float g_Lg[Mm];                 // last LSE for g  (g = -eps*Lg)
static __device__ float g_Lf[Nn];                 // LSE for f / f_out

// -------------------- prep: logs + initial vb (g=0) --------------------
__global__ void prep_kernel(const float* __restrict__ h, const float* __restrict__ hi) {
    int i = blockIdx.x * blockDim.x + threadIdx.x;
    if (i < Nn) g_la[i] = logf(h[i]);
    if (i < Mm) { float l = logf(hi[i]); g_lb[i] = l; g_vb[i] = l; }
}

// -------------------- projection GEMM: out = A[n,Dd] @ B[Dd,Dd]^T --------------------
template <int SEL>
__global__ void proj_gemm(const float* __restrict__ A, const float* __restrict__ B) {
    __shared__ float As[16][64];
    __shared__ float Bs[16][64];
    float* out = SEL ? g_Y : g_X;
    const int bi = blockIdx.y * 64, bj = blockIdx.x * 64;
    const int t  = threadIdx.x;
    const int tx = t & 15, ty = t >> 4;
    const int lr = t >> 2, lq = (t & 3) << 2;
    float acc[4][4] = {};
    const float* Ap = A + (size_t)(bi + lr) * Dd + lq;
    const float* Bp = B + (size_t)(bj + lr) * Dd + lq;
    for (int k0 = 0; k0 < Dd; k0 += 16) {
        float4 a4 = *(const float4*)(Ap + k0);
        float4 b4 = *(const float4*)(Bp + k0);
        As[lq + 0][lr] = a4.x; As[lq + 1][lr] = a4.y; As[lq + 2][lr] = a4.z; As[lq + 3][lr] = a4.w;
        Bs[lq + 0][lr] = b4.x; Bs[lq + 1][lr] = b4.y; Bs[lq + 2][lr] = b4.z; Bs[lq + 3][lr] = b4.w;
        __syncthreads();
        #pragma unroll
        for (int c = 0; c < 16; c++) {
            float a[4], b[4];
            *(float4*)a = *(const float4*)&As[c][ty << 2];
            *(float4*)b = *(const float4*)&Bs[c][tx << 2];
            #pragma unroll
            for (int ii = 0; ii < 4; ii++)
                #pragma unroll
                for (int jj = 0; jj < 4; jj++)
                    acc[ii][jj] = fmaf(a[ii], b[jj], acc[ii][jj]);
        }
        __syncthreads();
    }
    #pragma unroll
    for (int ii = 0; ii < 4; ii++) {
        int row = bi + (ty << 2) + ii;
        #pragma unroll
        for (int jj = 0; jj < 4; jj++)
            out[(size_t)row * Dd + bj + (tx << 2) + jj] = acc[ii][jj];
    }
}

// -------------------- row squared norms (times 0.5) --------------------
template <int SEL>
__global__ void rownorm_kernel() {
    const float* X = SEL ? g_Y : g_X;
    float* outn    = SEL ? g_ny : g_nx;
    const int row = blockIdx.x, t = threadIdx.x;
    const float* xr = X + (size_t)row * Dd;
    float s = 0.f;
    for (int c = t; c < Dd; c += 256) { float v = xr[c]; s = fmaf(v, v, s); }
    #pragma unroll
    for (int o = 16; o > 0; o >>= 1) s += __shfl_xor_sync(0xffffffffu, s, o);
    __shared__ float sm[8];
    if ((t & 31) == 0) sm[t >> 5] = s;
    __syncthreads();
    if (t == 0) {
        float tot = 0.f;
        #pragma unroll
        for (int w = 0; w < 8; w++) tot += sm[w];
        outn[row] = 0.5f * tot;
    }
}

// -------------------- cost: SC[i,j] = max(nx_i + ny_j - x_i.y_j, 0)/eps --------------------
__global__ void cost_kernel() {
    __shared__ float As[16][64];
    __shared__ float Bs[16][64];
    const int bi = blockIdx.y * 64, bj = blockIdx.x * 64;
    const int t  = threadIdx.x;
    const int tx = t & 15, ty = t >> 4;
    const int lr = t >> 2, lq = (t & 3) << 2;
    float acc[4][4] = {};
    const float* Ap = g_X + (size_t)(bi + lr) * Dd + lq;
    const float* Bp = g_Y + (size_t)(bj + lr) * Dd + lq;
    for (int k0 = 0; k0 < Dd; k0 += 16) {
        float4 a4 = *(const float4*)(Ap + k0);
        float4 b4 = *(const float4*)(Bp + k0);
        As[lq + 0][lr] = a4.x; As[lq + 1][lr] = a4.y; As[lq + 2][lr] = a4.z; As[lq + 3][lr] = a4.w;
        Bs[lq + 0][lr] = b4.x; Bs[lq + 1][lr] = b4.y; Bs[lq + 2][lr] = b4.z; Bs[lq + 3][lr] = b4.w;
        __syncthreads();
        #pragma unroll
        for (int c = 0; c < 16; c++) {
            float a[4], b[4];
            *(float4*)a = *(const float4*)&As[c][ty << 2];
            *(float4*)b = *(const float4*)&Bs[c][tx << 2];
            #pragma unroll
            for (int ii = 0; ii < 4; ii++)
                #pragma unroll
                for (int jj = 0; jj < 4; jj++)
                    acc[ii][jj] = fmaf(a[ii], b[jj], acc[ii][jj]);
        }
        __syncthreads();
    }
    #pragma unroll
    for (int ii = 0; ii < 4; ii++) {
        int i = bi + (ty << 2) + ii;
        float nxv = g_nx[i];
        #pragma unroll
        for (int jj = 0; jj < 4; jj++) {
            int j = bj + (tx << 2) + jj;
            float c = fmaxf(nxv + g_ny[j] - acc[ii][jj], 0.f) * 400.0f;  // /eps
            g_SC[(size_t)i * Mm + j] = c;
        }
    }
}

// -------------------- transpose SC -> SCT (coalesced both ways) --------------------
__global__ void transpose_kernel() {
    __shared__ float tile[32][33];
    const int bx = blockIdx.x << 5;  // M offset
    const int by = blockIdx.y << 5;  // N offset
    const int tx = threadIdx.x, ty = threadIdx.y;
    #pragma unroll
    for (int r = ty; r < 32; r += 8)
        tile[r][tx] = g_SC[(size_t)(by + r) * Mm + bx + tx];
    __syncthreads();
    #pragma unroll
    for (int r = ty; r < 32; r += 8)
        g_SCT[(size_t)(bx + r) * Nn + by + tx] = tile[tx][r];
}

// -------------------- streaming online log-sum-exp per row --------------------
// MODE 0: f-update  : L_i = LSE_j(vb_j - SC[i,j]),  va_i = la_i - L_i
// MODE 1: g-update  : L_j = LSE_i(va_i - SCT[j,i]), vb_j = lb_j - L_j, store Lg
// MODE 2: final f   : like MODE 0, store Lf only
template <int MODE>
__global__ void softmin_kernel() {
    const float* S   = (MODE == 1) ? g_SCT : g_SC;
    const int   cols = (MODE == 1) ? Nn : Mm;
    const float* v   = (MODE == 1) ? g_va : g_vb;
    const float* lg  = (MODE == 1) ? g_lb : g_la;
    float* vout      = (MODE == 0) ? g_va : ((MODE == 1) ? g_vb : nullptr);
    float* Lout      = (MODE == 1) ? g_Lg : g_Lf;

    const int row = blockIdx.x;
    const int t = threadIdx.x;
    const float4* Sr = (const float4*)(S + (size_t)row * cols);
    const float4* V4 = (const float4*)v;
    const int nq = cols >> 2;

    float m = -INFINITY, s = 0.f;
    for (int q = t; q < nq; q += 256) {
        float4 sv = Sr[q];
        float4 vv = V4[q];
        float a;
        a = vv.x - sv.x; if (a > m) { s = fmaf(s, __expf(m - a), 1.f); m = a; } else s += __expf(a - m);
        a = vv.y - sv.y; if (a > m) { s = fmaf(s, __expf(m - a), 1.f); m = a; } else s += __expf(a - m);
        a = vv.z - sv.z; if (a > m) { s = fmaf(s, __expf(m - a), 1.f); m = a; } else s += __expf(a - m);
        a = vv.w - sv.w; if (a > m) { s = fmaf(s, __expf(m - a), 1.f); m = a; } else s += __expf(a - m);
    }
    // warp combine
    #pragma unroll
    for (int o = 16; o > 0; o >>= 1) {
        float om = __shfl_xor_sync(0xffffffffu, m, o);
        float os = __shfl_xor_sync(0xffffffffu, s, o);
        float M2 = fmaxf(m, om);
        s = s * __expf(m - M2) + os * __expf(om - M2);
        m = M2;
    }
    __shared__ float sm[8], ss[8];
    if ((t & 31) == 0) { sm[t >> 5] = m; ss[t >> 5] = s; }
    __syncthreads();
    if (t == 0) {
        float M2 = sm[0], S2 = ss[0];
        #pragma unroll
        for (int w = 1; w < 8; w++) {
            float Mn = fmaxf(M2, sm[w]);
            S2 = S2 * __expf(M2 - Mn) + ss[w] * __expf(sm[w] - Mn);
            M2 = Mn;
        }
        float L = M2 + logf(S2);
        Lout[row] = L;
        if (MODE != 2) vout[row] = lg[row] - L;
    }
}

// -------------------- final scalar --------------------
// f_out = -eps*Lf ; g_out = -eps*Lg ; f_aa = -(eps/2)*la ; g_bb = -(eps/2)*lb
// S = sum h*(f_out - f_aa) + sum hi*(g_out - g_bb) = -eps * total
// out = exp(-S) = exp(eps * total)
__global__ void final_kernel(const float* __restrict__ h, const float* __restrict__ hi,
                             float* __restrict__ out) {
    const int t = threadIdx.x;
    double acc = 0.0;
    for (int i = t; i < Nn; i += 256)
        acc += (double)h[i] * ((double)g_Lf[i] - 0.5 * (double)g_la[i]);
    for (int j = t; j < Mm; j += 256)
        acc += (double)hi[j] * ((double)g_Lg[j] - 0.5 * (double)g_lb[j]);
    __shared__ double sd[256];
    sd[t] = acc;
    __syncthreads();
    for (int o = 128; o > 0; o >>= 1) {
        if (t < o) sd[t] += sd[t + o];
        __syncthreads();
    }
    if (t == 0) out[0] = (float)exp(EPS_D * sd[0]);
}

// -------------------- launch --------------------
extern "C" void kernel_launch(void* const* d_in, const int* in_sizes, int n_in,
                              void* d_out, int out_size) {
    const float *dp = nullptr, *sip = nullptr, *hp = nullptr, *hip = nullptr, *Wp = nullptr;
    for (int i = 0; i < n_in; i++) {
        switch (in_sizes[i]) {
            case Nn * Dd: dp  = (const float*)d_in[i]; break;
            case Mm * Dd: sip = (const float*)d_in[i]; break;
            case Nn:      hp  = (const float*)d_in[i]; break;
            case Mm:      hip = (const float*)d_in[i]; break;
            case Dd * Dd: Wp  = (const float*)d_in[i]; break;
        }
    }
    // fallback to positional order if size matching failed
    if (!dp)  dp  = (const float*)d_in[0];
    if (!sip) sip = (const float*)d_in[1];
    if (!hp)  hp  = (const float*)d_in[2];
    if (!hip) hip = (const float*)d_in[3];
    if (!Wp)  Wp  = (const float*)d_in[4];

    prep_kernel<<<(Nn + 255) / 256, 256>>>(hp, hip);
    proj_gemm<0><<<dim3(Dd / 64, Nn / 64), 256>>>(dp, Wp);
    proj_gemm<1><<<dim3(Dd / 64, Mm / 64), 256>>>(sip, Wp);
    rownorm_kernel<0><<<Nn, 256>>>();
    rownorm_kernel<1><<<Mm, 256>>>();
    cost_kernel<<<dim3(Mm / 64, Nn / 64), 256>>>();
    transpose_kernel<<<dim3(Mm / 32, Nn / 32), dim3(32, 8)>>>();

    for (int it = 0; it < 50; it++) {
        softmin_kernel<0><<<Nn, 256>>>();   // f-update over rows of SC
        softmin_kernel<1><<<Mm, 256>>>();   // g-update over rows of SCT
    }
    softmin_kernel<2><<<Nn, 256>>>();       // final differentiable f_out

    final_kernel<<<1, 256>>>(hp, hip, (float*)d_out);
}

// round 2
// speedup vs baseline: 1.0037x; 1.0037x over previous
#include <cuda_runtime.h>
#include <math.h>

#define Nn 8192
#define Mm 2048
#define Dd 768
// eps = blur^p = 0.05^2
#define EPS_D 0.0025

// -------- scratch (no allocations allowed; static device globals) --------
static __device__ float g_X[(size_t)Nn * Dd];     // x = d @ W^T
static __device__ float g_Y[(size_t)Mm * Dd];     // y = si @ W^T
static __device__ float g_SC[(size_t)Nn * Mm];    // C_xy / eps
static __device__ float g_SCT[(size_t)Mm * Nn];   // transpose
static __device__ float g_nx[Nn];                 // 0.5*|x_i|^2
static __device__ float g_ny[Mm];                 // 0.5*|y_j|^2
static __device__ float g_la[Nn];                 // log h
static __device__ float g_lb[Mm];                 // log hi
static __device__ float g_va[Nn];                 // la + f/eps
static __device__ float g_vb[Mm];                 // lb + g/eps
static __device__ float g_Lg[Mm];                 // last LSE for g  (g = -eps*Lg)
static __device__ float g_Lf[Nn];                 // LSE for f / f_out

// -------------------- prep: logs + initial vb (g=0) --------------------
__global__ void prep_kernel(const float* __restrict__ h, const float* __restrict__ hi) {
    int i = blockIdx.x * blockDim.x + threadIdx.x;
    if (i < Nn) g_la[i] = logf(h[i]);
    if (i < Mm) { float l = logf(hi[i]); g_lb[i] = l; g_vb[i] = l; }
}

// -------------------- projection GEMM: out = A[n,Dd] @ B[Dd,Dd]^T --------------------
template <int SEL>
__global__ void proj_gemm(const float* __restrict__ A, const float* __restrict__ B) {
    __shared__ float As[16][64];
    __shared__ float Bs[16][64];
    float* out = SEL ? g_Y : g_X;
    const int bi = blockIdx.y * 64, bj = blockIdx.x * 64;
    const int t  = threadIdx.x;
    const int tx = t & 15, ty = t >> 4;
    const int lr = t >> 2, lq = (t & 3) << 2;
    float acc[4][4] = {};
    const float* Ap = A + (size_t)(bi + lr) * Dd + lq;
    const float* Bp = B + (size_t)(bj + lr) * Dd + lq;
    for (int k0 = 0; k0 < Dd; k0 += 16) {
        float4 a4 = *(const float4*)(Ap + k0);
        float4 b4 = *(const float4*)(Bp + k0);
        As[lq + 0][lr] = a4.x; As[lq + 1][lr] = a4.y; As[lq + 2][lr] = a4.z; As[lq + 3][lr] = a4.w;
        Bs[lq + 0][lr] = b4.x; Bs[lq + 1][lr] = b4.y; Bs[lq + 2][lr] = b4.z; Bs[lq + 3][lr] = b4.w;
        __syncthreads();
        #pragma unroll
        for (int c = 0; c < 16; c++) {
            float a[4], b[4];
            *(float4*)a = *(const float4*)&As[c][ty << 2];
            *(float4*)b = *(const float4*)&Bs[c][tx << 2];
            #pragma unroll
            for (int ii = 0; ii < 4; ii++)
                #pragma unroll
                for (int jj = 0; jj < 4; jj++)
                    acc[ii][jj] = fmaf(a[ii], b[jj], acc[ii][jj]);
        }
        __syncthreads();
    }
    #pragma unroll
    for (int ii = 0; ii < 4; ii++) {
        int row = bi + (ty << 2) + ii;
        #pragma unroll
        for (int jj = 0; jj < 4; jj++)
            out[(size_t)row * Dd + bj + (tx << 2) + jj] = acc[ii][jj];
    }
}

// -------------------- row squared norms (times 0.5) --------------------
template <int SEL>
__global__ void rownorm_kernel() {
    const float* X = SEL ? g_Y : g_X;
    float* outn    = SEL ? g_ny : g_nx;
    const int row = blockIdx.x, t = threadIdx.x;
    const float* xr = X + (size_t)row * Dd;
    float s = 0.f;
    for (int c = t; c < Dd; c += 256) { float v = xr[c]; s = fmaf(v, v, s); }
    #pragma unroll
    for (int o = 16; o > 0; o >>= 1) s += __shfl_xor_sync(0xffffffffu, s, o);
    __shared__ float sm[8];
    if ((t & 31) == 0) sm[t >> 5] = s;
    __syncthreads();
    if (t == 0) {
        float tot = 0.f;
        #pragma unroll
        for (int w = 0; w < 8; w++) tot += sm[w];
        outn[row] = 0.5f * tot;
    }
}

// -------------------- cost: SC[i,j] = max(nx_i + ny_j - x_i.y_j, 0)/eps --------------------
__global__ void cost_kernel() {
    __shared__ float As[16][64];
    __shared__ float Bs[16][64];
    const int bi = blockIdx.y * 64, bj = blockIdx.x * 64;
    const int t  = threadIdx.x;
    const int tx = t & 15, ty = t >> 4;
    const int lr = t >> 2, lq = (t & 3) << 2;
    float acc[4][4] = {};
    const float* Ap = g_X + (size_t)(bi + lr) * Dd + lq;
    const float* Bp = g_Y + (size_t)(bj + lr) * Dd + lq;
    for (int k0 = 0; k0 < Dd; k0 += 16) {
        float4 a4 = *(const float4*)(Ap + k0);
        float4 b4 = *(const float4*)(Bp + k0);
        As[lq + 0][lr] = a4.x; As[lq + 1][lr] = a4.y; As[lq + 2][lr] = a4.z; As[lq + 3][lr] = a4.w;
        Bs[lq + 0][lr] = b4.x; Bs[lq + 1][lr] = b4.y; Bs[lq + 2][lr] = b4.z; Bs[lq + 3][lr] = b4.w;
        __syncthreads();
        #pragma unroll
        for (int c = 0; c < 16; c++) {
            float a[4], b[4];
            *(float4*)a = *(const float4*)&As[c][ty << 2];
            *(float4*)b = *(const float4*)&Bs[c][tx << 2];
            #pragma unroll
            for (int ii = 0; ii < 4; ii++)
                #pragma unroll
                for (int jj = 0; jj < 4; jj++)
                    acc[ii][jj] = fmaf(a[ii], b[jj], acc[ii][jj]);
        }
        __syncthreads();
    }
    #pragma unroll
    for (int ii = 0; ii < 4; ii++) {
        int i = bi + (ty << 2) + ii;
        float nxv = g_nx[i];
        #pragma unroll
        for (int jj = 0; jj < 4; jj++) {
            int j = bj + (tx << 2) + jj;
            float c = fmaxf(nxv + g_ny[j] - acc[ii][jj], 0.f) * 400.0f;  // /eps
            g_SC[(size_t)i * Mm + j] = c;
        }
    }
}

// -------------------- transpose SC -> SCT (coalesced both ways) --------------------
__global__ void transpose_kernel() {
    __shared__ float tile[32][33];
    const int bx = blockIdx.x << 5;  // M offset
    const int by = blockIdx.y << 5;  // N offset
    const int tx = threadIdx.x, ty = threadIdx.y;
    #pragma unroll
    for (int r = ty; r < 32; r += 8)
        tile[r][tx] = g_SC[(size_t)(by + r) * Mm + bx + tx];
    __syncthreads();
    #pragma unroll
    for (int r = ty; r < 32; r += 8)
        g_SCT[(size_t)(bx + r) * Nn + by + tx] = tile[tx][r];
}

// -------------------- streaming online log-sum-exp per row --------------------
// MODE 0: f-update  : L_i = LSE_j(vb_j - SC[i,j]),  va_i = la_i - L_i
// MODE 1: g-update  : L_j = LSE_i(va_i - SCT[j,i]), vb_j = lb_j - L_j, store Lg
// MODE 2: final f   : like MODE 0, store Lf only
template <int MODE>
__global__ void softmin_kernel() {
    const float* S   = (MODE == 1) ? g_SCT : g_SC;
    const int   cols = (MODE == 1) ? Nn : Mm;
    const float* v   = (MODE == 1) ? g_va : g_vb;
    const float* lg  = (MODE == 1) ? g_lb : g_la;
    float* vout      = (MODE == 0) ? g_va : ((MODE == 1) ? g_vb : nullptr);
    float* Lout      = (MODE == 1) ? g_Lg : g_Lf;

    const int row = blockIdx.x;
    const int t = threadIdx.x;
    const float4* Sr = (const float4*)(S + (size_t)row * cols);
    const float4* V4 = (const float4*)v;
    const int nq = cols >> 2;

    float m = -INFINITY, s = 0.f;
    for (int q = t; q < nq; q += 256) {
        float4 sv = Sr[q];
        float4 vv = V4[q];
        float a;
        a = vv.x - sv.x; if (a > m) { s = fmaf(s, __expf(m - a), 1.f); m = a; } else s += __expf(a - m);
        a = vv.y - sv.y; if (a > m) { s = fmaf(s, __expf(m - a), 1.f); m = a; } else s += __expf(a - m);
        a = vv.z - sv.z; if (a > m) { s = fmaf(s, __expf(m - a), 1.f); m = a; } else s += __expf(a - m);
        a = vv.w - sv.w; if (a > m) { s = fmaf(s, __expf(m - a), 1.f); m = a; } else s += __expf(a - m);
    }
    // warp combine
    #pragma unroll
    for (int o = 16; o > 0; o >>= 1) {
        float om = __shfl_xor_sync(0xffffffffu, m, o);
        float os = __shfl_xor_sync(0xffffffffu, s, o);
        float M2 = fmaxf(m, om);
        s = s * __expf(m - M2) + os * __expf(om - M2);
        m = M2;
    }
    __shared__ float sm[8], ss[8];
    if ((t & 31) == 0) { sm[t >> 5] = m; ss[t >> 5] = s; }
    __syncthreads();
    if (t == 0) {
        float M2 = sm[0], S2 = ss[0];
        #pragma unroll
        for (int w = 1; w < 8; w++) {
            float Mn = fmaxf(M2, sm[w]);
            S2 = S2 * __expf(M2 - Mn) + ss[w] * __expf(sm[w] - Mn);
            M2 = Mn;
        }
        float L = M2 + logf(S2);
        Lout[row] = L;
        if (MODE != 2) vout[row] = lg[row] - L;
    }
}

// -------------------- final scalar --------------------
// f_out = -eps*Lf ; g_out = -eps*Lg ; f_aa = -(eps/2)*la ; g_bb = -(eps/2)*lb
// S = sum h*(f_out - f_aa) + sum hi*(g_out - g_bb) = -eps * total
// out = exp(-S) = exp(eps * total)
__global__ void final_kernel(const float* __restrict__ h, const float* __restrict__ hi,
                             float* __restrict__ out) {
    const int t = threadIdx.x;
    double acc = 0.0;
    for (int i = t; i < Nn; i += 256)
        acc += (double)h[i] * ((double)g_Lf[i] - 0.5 * (double)g_la[i]);
    for (int j = t; j < Mm; j += 256)
        acc += (double)hi[j] * ((double)g_Lg[j] - 0.5 * (double)g_lb[j]);
    __shared__ double sd[256];
    sd[t] = acc;
    __syncthreads();
    for (int o = 128; o > 0; o >>= 1) {
        if (t < o) sd[t] += sd[t + o];
        __syncthreads();
    }
    if (t == 0) out[0] = (float)exp(EPS_D * sd[0]);
}

// -------------------- launch --------------------
extern "C" void kernel_launch(void* const* d_in, const int* in_sizes, int n_in,
                              void* d_out, int out_size) {
    const float *dp = nullptr, *sip = nullptr, *hp = nullptr, *hip = nullptr, *Wp = nullptr;
    for (int i = 0; i < n_in; i++) {
        switch (in_sizes[i]) {
            case Nn * Dd: dp  = (const float*)d_in[i]; break;
            case Mm * Dd: sip = (const float*)d_in[i]; break;
            case Nn:      hp  = (const float*)d_in[i]; break;
            case Mm:      hip = (const float*)d_in[i]; break;
            case Dd * Dd: Wp  = (const float*)d_in[i]; break;
        }
    }
    // fallback to positional order if size matching failed
    if (!dp)  dp  = (const float*)d_in[0];
    if (!sip) sip = (const float*)d_in[1];
    if (!hp)  hp  = (const float*)d_in[2];
    if (!hip) hip = (const float*)d_in[3];
    if (!Wp)  Wp  = (const float*)d_in[4];

    prep_kernel<<<(Nn + 255) / 256, 256>>>(hp, hip);
    proj_gemm<0><<<dim3(Dd / 64, Nn / 64), 256>>>(dp, Wp);
    proj_gemm<1><<<dim3(Dd / 64, Mm / 64), 256>>>(sip, Wp);
    rownorm_kernel<0><<<Nn, 256>>>();
    rownorm_kernel<1><<<Mm, 256>>>();
    cost_kernel<<<dim3(Mm / 64, Nn / 64), 256>>>();
    transpose_kernel<<<dim3(Mm / 32, Nn / 32), dim3(32, 8)>>>();

    for (int it = 0; it < 50; it++) {
        softmin_kernel<0><<<Nn, 256>>>();   // f-update over rows of SC
        softmin_kernel<1><<<Mm, 256>>>();   // g-update over rows of SCT
    }
    softmin_kernel<2><<<Nn, 256>>>();       // final differentiable f_out

    final_kernel<<<1, 256>>>(hp, hip, (float*)d_out);
}

// round 3
// speedup vs baseline: 1.7433x; 1.7370x over previous
#include <cuda_runtime.h>
#include <cuda_fp16.h>
#include <math.h>
#include <stdint.h>

#define Nn 8192
#define Mm 2048
#define Dd 768
#define EPS_D 0.0025

static __device__ float g_X[(size_t)Nn * Dd];
static __device__ float g_Y[(size_t)Mm * Dd];
static __device__ __half g_H[(size_t)Nn * Mm];   // SC - off_i
static __device__ __half g_HT[(size_t)Mm * Nn];
static __device__ float g_nx[Nn], g_ny[Mm], g_off[Nn];
static __device__ float g_la[Nn], g_lb[Mm];
static __device__ float g_wa[Nn];   // la - L'
static __device__ float g_vb[Mm];   // lb + g/eps
static __device__ float g_Lf[Nn], g_Lg[Mm];
static __device__ float g_nybar;

__device__ __forceinline__ uint32_t tf32r(float x) {
    uint32_t u; asm("cvt.rna.tf32.f32 %0, %1;" : "=r"(u) : "f"(x)); return u;
}

__global__ void prep_kernel(const float* __restrict__ h, const float* __restrict__ hi) {
    int i = blockIdx.x * blockDim.x + threadIdx.x;
    if (i < Nn) g_la[i] = logf(h[i]);
    if (i < Mm) { float l = logf(hi[i]); g_lb[i] = l; g_vb[i] = l; }
}

// ============ tf32 tensor-core GEMM: OUT = A[nA,768] @ B[nB,768]^T ============
// block tile 128x64, 256 threads (8 warps: wm = wid&1 -> 64 rows, wn = wid>>1 -> 16 cols)
// EPI=0: write fp32 Fout (ld=ldc).  EPI=1: cost epilogue -> g_H fp16.
template <int EPI>
__global__ void __launch_bounds__(256) tf32_gemm(const float* __restrict__ A,
                                                 const float* __restrict__ B,
                                                 float* __restrict__ Fout, int ldc) {
    __shared__ uint32_t As[128][36];
    __shared__ uint32_t Bs[64][36];
    const int t = threadIdx.x, lane = t & 31, wid = t >> 5;
    const int wm = wid & 1, wn = wid >> 1;
    const int bi = blockIdx.y * 128, bj = blockIdx.x * 64;
    const int ar = t >> 3, ac = (t & 7) * 4;

    float acc[4][2][4];
    #pragma unroll
    for (int a = 0; a < 4; a++)
        #pragma unroll
        for (int b = 0; b < 2; b++)
            #pragma unroll
            for (int c = 0; c < 4; c++) acc[a][b][c] = 0.f;

    float4 pa[4], pb[2];
    #pragma unroll
    for (int p = 0; p < 4; p++) pa[p] = *(const float4*)(A + (size_t)(bi + ar + 32 * p) * Dd + ac);
    #pragma unroll
    for (int p = 0; p < 2; p++) pb[p] = *(const float4*)(B + (size_t)(bj + ar + 32 * p) * Dd + ac);

    const int tg = lane & 3, gp = lane >> 2;
    for (int ch = 0; ch < 24; ch++) {
        #pragma unroll
        for (int p = 0; p < 4; p++) {
            uint4 q = make_uint4(tf32r(pa[p].x), tf32r(pa[p].y), tf32r(pa[p].z), tf32r(pa[p].w));
            *(uint4*)&As[ar + 32 * p][ac] = q;
        }
        #pragma unroll
        for (int p = 0; p < 2; p++) {
            uint4 q = make_uint4(tf32r(pb[p].x), tf32r(pb[p].y), tf32r(pb[p].z), tf32r(pb[p].w));
            *(uint4*)&Bs[ar + 32 * p][ac] = q;
        }
        __syncthreads();
        if (ch < 23) {
            const int k0 = (ch + 1) * 32;
            #pragma unroll
            for (int p = 0; p < 4; p++) pa[p] = *(const float4*)(A + (size_t)(bi + ar + 32 * p) * Dd + k0 + ac);
            #pragma unroll
            for (int p = 0; p < 2; p++) pb[p] = *(const float4*)(B + (size_t)(bj + ar + 32 * p) * Dd + k0 + ac);
        }
        #pragma unroll
        for (int kk = 0; kk < 4; kk++) {
            uint32_t ua[4][4], ub[2][2];
            const int kc = kk * 8 + tg;
            #pragma unroll
            for (int im = 0; im < 4; im++) {
                const int rA = wm * 64 + im * 16 + gp;
                ua[im][0] = As[rA][kc];     ua[im][1] = As[rA + 8][kc];
                ua[im][2] = As[rA][kc + 4]; ua[im][3] = As[rA + 8][kc + 4];
            }
            #pragma unroll
            for (int jn = 0; jn < 2; jn++) {
                const int rB = wn * 16 + jn * 8 + gp;
                ub[jn][0] = Bs[rB][kc]; ub[jn][1] = Bs[rB][kc + 4];
            }
            #pragma unroll
            for (int im = 0; im < 4; im++)
                #pragma unroll
                for (int jn = 0; jn < 2; jn++)
                    asm volatile(
                        "mma.sync.aligned.m16n8k8.row.col.f32.tf32.tf32.f32 "
                        "{%0,%1,%2,%3}, {%4,%5,%6,%7}, {%8,%9}, {%0,%1,%2,%3};"
                        : "+f"(acc[im][jn][0]), "+f"(acc[im][jn][1]),
                          "+f"(acc[im][jn][2]), "+f"(acc[im][jn][3])
                        : "r"(ua[im][0]), "r"(ua[im][1]), "r"(ua[im][2]), "r"(ua[im][3]),
                          "r"(ub[jn][0]), "r"(ub[jn][1]));
        }
        __syncthreads();
    }

    const float nyb = (EPI == 1) ? g_nybar : 0.f;
    #pragma unroll
    for (int im = 0; im < 4; im++) {
        const int r0 = bi + wm * 64 + im * 16 + gp;
        #pragma unroll
        for (int jn = 0; jn < 2; jn++) {
            const int cb = bj + wn * 16 + jn * 8 + 2 * tg;
            if (EPI == 0) {
                *(float2*)(Fout + (size_t)r0 * ldc + cb) = make_float2(acc[im][jn][0], acc[im][jn][1]);
                *(float2*)(Fout + (size_t)(r0 + 8) * ldc + cb) = make_float2(acc[im][jn][2], acc[im][jn][3]);
            } else {
                const float ny0 = g_ny[cb], ny1 = g_ny[cb + 1];
                const float nx0 = g_nx[r0], nx1 = g_nx[r0 + 8];
                float v00 = 400.f * fmaxf(nx0 + ny0 - acc[im][jn][0], 0.f) - 400.f * (nx0 + nyb);
                float v01 = 400.f * fmaxf(nx0 + ny1 - acc[im][jn][1], 0.f) - 400.f * (nx0 + nyb);
                float v10 = 400.f * fmaxf(nx1 + ny0 - acc[im][jn][2], 0.f) - 400.f * (nx1 + nyb);
                float v11 = 400.f * fmaxf(nx1 + ny1 - acc[im][jn][3], 0.f) - 400.f * (nx1 + nyb);
                *(__half2*)(g_H + (size_t)r0 * Mm + cb) = __floats2half2_rn(v00, v01);
                *(__half2*)(g_H + (size_t)(r0 + 8) * Mm + cb) = __floats2half2_rn(v10, v11);
            }
        }
    }
}

template <int SEL>
__global__ void rownorm_kernel() {
    const float* X = SEL ? g_Y : g_X;
    float* outn    = SEL ? g_ny : g_nx;
    const int row = blockIdx.x, t = threadIdx.x;
    const float* xr = X + (size_t)row * Dd;
    float s = 0.f;
    for (int c = t; c < Dd; c += 256) { float v = xr[c]; s = fmaf(v, v, s); }
    #pragma unroll
    for (int o = 16; o > 0; o >>= 1) s += __shfl_xor_sync(0xffffffffu, s, o);
    __shared__ float sm[8];
    if ((t & 31) == 0) sm[t >> 5] = s;
    __syncthreads();
    if (t == 0) {
        float tot = 0.f;
        #pragma unroll
        for (int w = 0; w < 8; w++) tot += sm[w];
        outn[row] = 0.5f * tot;
    }
}

__global__ void nybar_kernel() {
    const int t = threadIdx.x;
    float s = 0.f;
    for (int j = t; j < Mm; j += 256) s += g_ny[j];
    __shared__ float sd[256];
    sd[t] = s; __syncthreads();
    for (int o = 128; o > 0; o >>= 1) { if (t < o) sd[t] += sd[t + o]; __syncthreads(); }
    if (t == 0) g_nybar = sd[0] / (float)Mm;
}

__global__ void off_kernel() {
    int i = blockIdx.x * blockDim.x + threadIdx.x;
    if (i < Nn) g_off[i] = 400.f * (g_nx[i] + g_nybar);
}

__global__ void transpose_kernel() {
    __shared__ unsigned short tile[32][33];
    const int bx = blockIdx.x << 5, by = blockIdx.y << 5;
    const int tx = threadIdx.x, ty = threadIdx.y;
    #pragma unroll
    for (int r = ty; r < 32; r += 8)
        tile[r][tx] = ((const unsigned short*)g_H)[(size_t)(by + r) * Mm + bx + tx];
    __syncthreads();
    #pragma unroll
    for (int r = ty; r < 32; r += 8)
        ((unsigned short*)g_HT)[(size_t)(bx + r) * Nn + by + tx] = tile[tx][r];
}

#define ONL(aa) { float a_ = (aa); if (a_ > m) { s = fmaf(s, __expf(m - a_), 1.f); m = a_; } else s += __expf(a_ - m); }

// rows of H (8192 x 2048 fp16). FINAL=0: wa = la - L'.  FINAL=1: Lf = L'.
template <int FINAL>
__global__ void __launch_bounds__(256) softminA() {
    const int t = threadIdx.x, lane = t & 31;
    const int row = blockIdx.x * 8 + (t >> 5);
    const uint4* Hr = (const uint4*)(g_H + (size_t)row * Mm);
    float m = -1e30f, s = 0.f;
    #pragma unroll
    for (int q = 0; q < 8; q++) {
        const int idx = q * 32 + lane;
        uint4 u = Hr[idx];
        const int c0 = idx * 8;
        float4 v0 = __ldg((const float4*)(g_vb + c0));
        float4 v1 = __ldg((const float4*)(g_vb + c0 + 4));
        float2 f;
        f = __half22float2(*(__half2*)&u.x); ONL(v0.x - f.x); ONL(v0.y - f.y);
        f = __half22float2(*(__half2*)&u.y); ONL(v0.z - f.x); ONL(v0.w - f.y);
        f = __half22float2(*(__half2*)&u.z); ONL(v1.x - f.x); ONL(v1.y - f.y);
        f = __half22float2(*(__half2*)&u.w); ONL(v1.z - f.x); ONL(v1.w - f.y);
    }
    #pragma unroll
    for (int o = 16; o > 0; o >>= 1) {
        float om = __shfl_xor_sync(0xffffffffu, m, o);
        float os = __shfl_xor_sync(0xffffffffu, s, o);
        float M2 = fmaxf(m, om);
        s = s * __expf(m - M2) + os * __expf(om - M2);
        m = M2;
    }
    if (lane == 0) {
        float L = m + logf(s);
        if (FINAL) g_Lf[row] = L; else g_wa[row] = g_la[row] - L;
    }
}

// rows of HT (2048 x 8192 fp16), 2 warps per row. vb = lb - L; Lg = L.
__global__ void __launch_bounds__(256) softminB() {
    const int t = threadIdx.x, lane = t & 31, wid = t >> 5;
    const int row = blockIdx.x * 4 + (wid >> 1);
    const int half = wid & 1;
    const uint4* Hr = (const uint4*)(g_HT + (size_t)row * Nn);
    float m = -1e30f, s = 0.f;
    for (int q = half * 16; q < half * 16 + 16; q++) {
        const int idx = q * 32 + lane;
        uint4 u = Hr[idx];
        const int c0 = idx * 8;
        float4 v0 = __ldg((const float4*)(g_wa + c0));
        float4 v1 = __ldg((const float4*)(g_wa + c0 + 4));
        float2 f;
        f = __half22float2(*(__half2*)&u.x); ONL(v0.x - f.x); ONL(v0.y - f.y);
        f = __half22float2(*(__half2*)&u.y); ONL(v0.z - f.x); ONL(v0.w - f.y);
        f = __half22float2(*(__half2*)&u.z); ONL(v1.x - f.x); ONL(v1.y - f.y);
        f = __half22float2(*(__half2*)&u.w); ONL(v1.z - f.x); ONL(v1.w - f.y);
    }
    #pragma unroll
    for (int o = 16; o > 0; o >>= 1) {
        float om = __shfl_xor_sync(0xffffffffu, m, o);
        float os = __shfl_xor_sync(0xffffffffu, s, o);
        float M2 = fmaxf(m, om);
        s = s * __expf(m - M2) + os * __expf(om - M2);
        m = M2;
    }
    __shared__ float sm2[8], ss2[8];
    if (lane == 0) { sm2[wid] = m; ss2[wid] = s; }
    __syncthreads();
    if (t < 4) {
        float m0 = sm2[2 * t], s0 = ss2[2 * t], m1 = sm2[2 * t + 1], s1 = ss2[2 * t + 1];
        float M2 = fmaxf(m0, m1);
        float S2 = s0 * __expf(m0 - M2) + s1 * __expf(m1 - M2);
        float L = M2 + logf(S2);
        const int r = blockIdx.x * 4 + t;
        g_vb[r] = g_lb[r] - L;
        g_Lg[r] = L;
    }
}

__global__ void final_kernel(const float* __restrict__ h, const float* __restrict__ hi,
                             float* __restrict__ out) {
    const int t = threadIdx.x;
    double acc = 0.0;
    for (int i = t; i < Nn; i += 256)
        acc += (double)h[i] * ((double)g_Lf[i] - (double)g_off[i] - 0.5 * (double)g_la[i]);
    for (int j = t; j < Mm; j += 256)
        acc += (double)hi[j] * ((double)g_Lg[j] - 0.5 * (double)g_lb[j]);
    __shared__ double sd[256];
    sd[t] = acc; __syncthreads();
    for (int o = 128; o > 0; o >>= 1) { if (t < o) sd[t] += sd[t + o]; __syncthreads(); }
    if (t == 0) out[0] = (float)exp(EPS_D * sd[0]);
}

extern "C" void kernel_launch(void* const* d_in, const int* in_sizes, int n_in,
                              void* d_out, int out_size) {
    const float *dp = nullptr, *sip = nullptr, *hp = nullptr, *hip = nullptr, *Wp = nullptr;
    for (int i = 0; i < n_in; i++) {
        switch (in_sizes[i]) {
            case Nn * Dd: dp  = (const float*)d_in[i]; break;
            case Mm * Dd: sip = (const float*)d_in[i]; break;
            case Nn:      hp  = (const float*)d_in[i]; break;
            case Mm:      hip = (const float*)d_in[i]; break;
            case Dd * Dd: Wp  = (const float*)d_in[i]; break;
        }
    }
    if (!dp)  dp  = (const float*)d_in[0];
    if (!sip) sip = (const float*)d_in[1];
    if (!hp)  hp  = (const float*)d_in[2];
    if (!hip) hip = (const float*)d_in[3];
    if (!Wp)  Wp  = (const float*)d_in[4];

    float* gX; cudaGetSymbolAddress((void**)&gX, g_X);
    float* gY; cudaGetSymbolAddress((void**)&gY, g_Y);

    prep_kernel<<<(Nn + 255) / 256, 256>>>(hp, hip);
    tf32_gemm<0><<<dim3(Dd / 64, Nn / 128), 256>>>(dp, Wp, gX, Dd);
    tf32_gemm<0><<<dim3(Dd / 64, Mm / 128), 256>>>(sip, Wp, gY, Dd);
    rownorm_kernel<0><<<Nn, 256>>>();
    rownorm_kernel<1><<<Mm, 256>>>();
    nybar_kernel<<<1, 256>>>();
    off_kernel<<<(Nn + 255) / 256, 256>>>();
    tf32_gemm<1><<<dim3(Mm / 64, Nn / 128), 256>>>(gX, gY, nullptr, 0);
    transpose_kernel<<<dim3(Mm / 32, Nn / 32), dim3(32, 8)>>>();

    for (int it = 0; it < 50; it++) {
        softminA<0><<<Nn / 8, 256>>>();
        softminB<<<Mm / 4, 256>>>();
    }
    softminA<1><<<Nn / 8, 256>>>();

    final_kernel<<<1, 256>>>(hp, hip, (float*)d_out);
}

// round 5
// speedup vs baseline: 3.4704x; 1.9906x over previous
#include <cuda_runtime.h>
#include <cuda_fp16.h>
#include <math.h>
#include <stdint.h>

#define Nn 8192
#define Mm 2048
#define Dd 768
#define EPS_D 0.0025
#define L2E 1.4426950408889634f
#define LN2 0.6931471805599453
#define SCL (400.0f * L2E)   // cost scale in log2 units

static __device__ float g_X[(size_t)Nn * Dd];
static __device__ float g_Y[(size_t)Mm * Dd];
static __device__ __align__(16) __half g_H[(size_t)Nn * Mm];   // (SC - off_i)*L2E
static __device__ __align__(16) __half g_HT[(size_t)Mm * Nn];
static __device__ float g_nx[Nn], g_ny[Mm], g_off[Nn];          // off in ln units
static __device__ float g_la[Nn], g_lb[Mm];                     // ln units
static __device__ float g_la2[Nn], g_lb2[Mm];                   // log2 units
static __device__ __align__(16) __half g_wah[Nn];               // wa2 (log2) fp16
static __device__ __align__(16) __half g_vbh[Mm];               // vb2 (log2) fp16
static __device__ float g_L2f[Nn], g_Lg2[Mm];                   // log2-LSE outputs
static __device__ float g_nybar;

__device__ __forceinline__ uint32_t tf32r(float x) {
    uint32_t u; asm("cvt.rna.tf32.f32 %0, %1;" : "=r"(u) : "f"(x)); return u;
}
__device__ __forceinline__ __half2 hexp2_(__half2 x) {
    uint32_t xi = *reinterpret_cast<uint32_t*>(&x), yi;
    asm("ex2.approx.f16x2 %0, %1;" : "=r"(yi) : "r"(xi));
    return *reinterpret_cast<__half2*>(&yi);
}

__global__ void prep_kernel(const float* __restrict__ h, const float* __restrict__ hi) {
    int i = blockIdx.x * blockDim.x + threadIdx.x;
    if (i < Nn) { float l = logf(h[i]); g_la[i] = l; g_la2[i] = l * L2E; }
    if (i < Mm) {
        float l = logf(hi[i]);
        g_lb[i] = l; g_lb2[i] = l * L2E;
        g_vbh[i] = __float2half(l * L2E);
    }
}

// ============ tf32 GEMM: OUT = A @ B^T. EPI=0: fp32 out. EPI=1: cost -> H (+HT fused) ============
template <int EPI>
__global__ void __launch_bounds__(256) tf32_gemm(const float* __restrict__ A,
                                                 const float* __restrict__ B,
                                                 float* __restrict__ Fout, int ldc) {
    __shared__ union U {
        struct { uint32_t As[128][36]; uint32_t Bs[64][36]; } k;
        __half tile[64][136];   // 272B rows (16B multiple)
    } su;
    uint32_t (&As)[128][36] = su.k.As;
    uint32_t (&Bs)[64][36] = su.k.Bs;

    const int t = threadIdx.x, lane = t & 31, wid = t >> 5;
    const int wm = wid & 1, wn = wid >> 1;
    const int bi = blockIdx.y * 128, bj = blockIdx.x * 64;
    const int ar = t >> 3, ac = (t & 7) * 4;

    float acc[4][2][4];
    #pragma unroll
    for (int a = 0; a < 4; a++)
        #pragma unroll
        for (int b = 0; b < 2; b++)
            #pragma unroll
            for (int c = 0; c < 4; c++) acc[a][b][c] = 0.f;

    float4 pa[4], pb[2];
    #pragma unroll
    for (int p = 0; p < 4; p++) pa[p] = *(const float4*)(A + (size_t)(bi + ar + 32 * p) * Dd + ac);
    #pragma unroll
    for (int p = 0; p < 2; p++) pb[p] = *(const float4*)(B + (size_t)(bj + ar + 32 * p) * Dd + ac);

    const int tg = lane & 3, gp = lane >> 2;
    for (int ch = 0; ch < 24; ch++) {
        #pragma unroll
        for (int p = 0; p < 4; p++)
            *(uint4*)&As[ar + 32 * p][ac] = make_uint4(tf32r(pa[p].x), tf32r(pa[p].y), tf32r(pa[p].z), tf32r(pa[p].w));
        #pragma unroll
        for (int p = 0; p < 2; p++)
            *(uint4*)&Bs[ar + 32 * p][ac] = make_uint4(tf32r(pb[p].x), tf32r(pb[p].y), tf32r(pb[p].z), tf32r(pb[p].w));
        __syncthreads();
        if (ch < 23) {
            const int k0 = (ch + 1) * 32;
            #pragma unroll
            for (int p = 0; p < 4; p++) pa[p] = *(const float4*)(A + (size_t)(bi + ar + 32 * p) * Dd + k0 + ac);
            #pragma unroll
            for (int p = 0; p < 2; p++) pb[p] = *(const float4*)(B + (size_t)(bj + ar + 32 * p) * Dd + k0 + ac);
        }
        #pragma unroll
        for (int kk = 0; kk < 4; kk++) {
            uint32_t ua[4][4], ub[2][2];
            const int kc = kk * 8 + tg;
            #pragma unroll
            for (int im = 0; im < 4; im++) {
                const int rA = wm * 64 + im * 16 + gp;
                ua[im][0] = As[rA][kc];     ua[im][1] = As[rA + 8][kc];
                ua[im][2] = As[rA][kc + 4]; ua[im][3] = As[rA + 8][kc + 4];
            }
            #pragma unroll
            for (int jn = 0; jn < 2; jn++) {
                const int rB = wn * 16 + jn * 8 + gp;
                ub[jn][0] = Bs[rB][kc]; ub[jn][1] = Bs[rB][kc + 4];
            }
            #pragma unroll
            for (int im = 0; im < 4; im++)
                #pragma unroll
                for (int jn = 0; jn < 2; jn++)
                    asm volatile(
                        "mma.sync.aligned.m16n8k8.row.col.f32.tf32.tf32.f32 "
                        "{%0,%1,%2,%3}, {%4,%5,%6,%7}, {%8,%9}, {%0,%1,%2,%3};"
                        : "+f"(acc[im][jn][0]), "+f"(acc[im][jn][1]),
                          "+f"(acc[im][jn][2]), "+f"(acc[im][jn][3])
                        : "r"(ua[im][0]), "r"(ua[im][1]), "r"(ua[im][2]), "r"(ua[im][3]),
                          "r"(ub[jn][0]), "r"(ub[jn][1]));
        }
        __syncthreads();
    }

    if (EPI == 0) {
        #pragma unroll
        for (int im = 0; im < 4; im++) {
            const int r0 = bi + wm * 64 + im * 16 + gp;
            #pragma unroll
            for (int jn = 0; jn < 2; jn++) {
                const int cb = bj + wn * 16 + jn * 8 + 2 * tg;
                *(float2*)(Fout + (size_t)r0 * ldc + cb) = make_float2(acc[im][jn][0], acc[im][jn][1]);
                *(float2*)(Fout + (size_t)(r0 + 8) * ldc + cb) = make_float2(acc[im][jn][2], acc[im][jn][3]);
            }
        }
    } else {
        const float nyb = g_nybar;
        __half2 hv[4][2][2];
        #pragma unroll
        for (int im = 0; im < 4; im++) {
            const int rl = wm * 64 + im * 16 + gp;
            const float nx0 = g_nx[bi + rl], nx1 = g_nx[bi + rl + 8];
            const float o0 = SCL * (nx0 + nyb), o1 = SCL * (nx1 + nyb);
            #pragma unroll
            for (int jn = 0; jn < 2; jn++) {
                const int cl = wn * 16 + jn * 8 + 2 * tg;
                const float ny0 = g_ny[bj + cl], ny1 = g_ny[bj + cl + 1];
                float v00 = SCL * fmaxf(nx0 + ny0 - acc[im][jn][0], 0.f) - o0;
                float v01 = SCL * fmaxf(nx0 + ny1 - acc[im][jn][1], 0.f) - o0;
                float v10 = SCL * fmaxf(nx1 + ny0 - acc[im][jn][2], 0.f) - o1;
                float v11 = SCL * fmaxf(nx1 + ny1 - acc[im][jn][3], 0.f) - o1;
                hv[im][jn][0] = __floats2half2_rn(v00, v01);
                hv[im][jn][1] = __floats2half2_rn(v10, v11);
                *(__half2*)(g_H + (size_t)(bi + rl) * Mm + bj + cl) = hv[im][jn][0];
                *(__half2*)(g_H + (size_t)(bi + rl + 8) * Mm + bj + cl) = hv[im][jn][1];
            }
        }
        __syncthreads();   // done with As/Bs; reuse as transpose tile
        #pragma unroll
        for (int im = 0; im < 4; im++) {
            const int rl = wm * 64 + im * 16 + gp;
            #pragma unroll
            for (int jn = 0; jn < 2; jn++) {
                const int cl = wn * 16 + jn * 8 + 2 * tg;
                su.tile[cl][rl]         = __low2half(hv[im][jn][0]);
                su.tile[cl + 1][rl]     = __high2half(hv[im][jn][0]);
                su.tile[cl][rl + 8]     = __low2half(hv[im][jn][1]);
                su.tile[cl + 1][rl + 8] = __high2half(hv[im][jn][1]);
            }
        }
        __syncthreads();
        const int c = t >> 2, rseg = (t & 3) * 32;
        const uint4* src = (const uint4*)&su.tile[c][rseg];
        uint4* dst = (uint4*)(g_HT + (size_t)(bj + c) * Nn + bi + rseg);
        #pragma unroll
        for (int q = 0; q < 4; q++) dst[q] = src[q];
    }
}

template <int SEL>
__global__ void rownorm_kernel() {
    const float* X = SEL ? g_Y : g_X;
    float* outn    = SEL ? g_ny : g_nx;
    const int row = blockIdx.x, t = threadIdx.x;
    const float* xr = X + (size_t)row * Dd;
    float s = 0.f;
    for (int c = t; c < Dd; c += 256) { float v = xr[c]; s = fmaf(v, v, s); }
    #pragma unroll
    for (int o = 16; o > 0; o >>= 1) s += __shfl_xor_sync(0xffffffffu, s, o);
    __shared__ float sm[8];
    if ((t & 31) == 0) sm[t >> 5] = s;
    __syncthreads();
    if (t == 0) {
        float tot = 0.f;
        #pragma unroll
        for (int w = 0; w < 8; w++) tot += sm[w];
        outn[row] = 0.5f * tot;
    }
}

__global__ void nybar_kernel() {
    const int t = threadIdx.x;
    float s = 0.f;
    for (int j = t; j < Mm; j += 256) s += g_ny[j];
    __shared__ float sd[256];
    sd[t] = s; __syncthreads();
    for (int o = 128; o > 0; o >>= 1) { if (t < o) sd[t] += sd[t + o]; __syncthreads(); }
    if (t == 0) g_nybar = sd[0] / (float)Mm;
}

__global__ void off_kernel() {
    int i = blockIdx.x * blockDim.x + threadIdx.x;
    if (i < Nn) g_off[i] = 400.f * (g_nx[i] + g_nybar);
}

// ============ two-pass half2 softmin over H rows (2048 cols, 1 warp/row) ============
// FINAL=0: wa2 = la2 - L. FINAL=1: store L2f.
template <int FINAL>
__global__ void __launch_bounds__(256) softminA() {
    const int t = threadIdx.x, lane = t & 31, wid = t >> 5;
    const int row = blockIdx.x * 8 + wid;
    const uint4* Hr = (const uint4*)(g_H + (size_t)row * Mm);
    const uint4* Vr = (const uint4*)g_vbh;

    __half2 a[8][4];
    __half2 m2 = __float2half2_rn(-60000.f);
    #pragma unroll
    for (int q = 0; q < 8; q++) {
        const int idx = q * 32 + lane;
        uint4 hu = Hr[idx];
        uint4 vu = __ldg(&Vr[idx]);
        const __half2* hp = (const __half2*)&hu;
        const __half2* vp = (const __half2*)&vu;
        #pragma unroll
        for (int c = 0; c < 4; c++) {
            a[q][c] = __hsub2(vp[c], hp[c]);
            m2 = __hmax2(m2, a[q][c]);
        }
    }
    float m = fmaxf(__half2float(__low2half(m2)), __half2float(__high2half(m2)));
    #pragma unroll
    for (int o = 16; o > 0; o >>= 1) m = fmaxf(m, __shfl_xor_sync(0xffffffffu, m, o));
    const __half2 mh = __float2half2_rn(m);

    float s0 = 0.f, s1 = 0.f;
    #pragma unroll
    for (int q = 0; q < 8; q++) {
        __half2 p = __float2half2_rn(0.f);
        #pragma unroll
        for (int c = 0; c < 4; c++) p = __hadd2(p, hexp2_(__hsub2(a[q][c], mh)));
        float pf = __half2float(__hadd(__low2half(p), __high2half(p)));
        if (q & 1) s1 += pf; else s0 += pf;
    }
    float s = s0 + s1;
    #pragma unroll
    for (int o = 16; o > 0; o >>= 1) s += __shfl_xor_sync(0xffffffffu, s, o);
    if (lane == 0) {
        float L = m + __log2f(s);
        if (FINAL) g_L2f[row] = L;
        else g_wah[row] = __float2half(g_la2[row] - L);
    }
}

// ============ softmin over HT rows (8192 cols, 4 warps/row, 2 rows/block) ============
__global__ void __launch_bounds__(256) softminB() {
    const int t = threadIdx.x, lane = t & 31, wid = t >> 5;
    const int rloc = wid >> 2, quarter = wid & 3;
    const int row = blockIdx.x * 2 + rloc;
    const uint4* Hr = (const uint4*)(g_HT + (size_t)row * Nn);
    const uint4* Vr = (const uint4*)g_wah;

    __half2 a[8][4];
    __half2 m2 = __float2half2_rn(-60000.f);
    #pragma unroll
    for (int q = 0; q < 8; q++) {
        const int idx = quarter * 256 + q * 32 + lane;
        uint4 hu = Hr[idx];
        uint4 vu = __ldg(&Vr[idx]);
        const __half2* hp = (const __half2*)&hu;
        const __half2* vp = (const __half2*)&vu;
        #pragma unroll
        for (int c = 0; c < 4; c++) {
            a[q][c] = __hsub2(vp[c], hp[c]);
            m2 = __hmax2(m2, a[q][c]);
        }
    }
    float m = fmaxf(__half2float(__low2half(m2)), __half2float(__high2half(m2)));
    #pragma unroll
    for (int o = 16; o > 0; o >>= 1) m = fmaxf(m, __shfl_xor_sync(0xffffffffu, m, o));
    const __half2 mh = __float2half2_rn(m);

    float s0 = 0.f, s1 = 0.f;
    #pragma unroll
    for (int q = 0; q < 8; q++) {
        __half2 p = __float2half2_rn(0.f);
        #pragma unroll
        for (int c = 0; c < 4; c++) p = __hadd2(p, hexp2_(__hsub2(a[q][c], mh)));
        float pf = __half2float(__hadd(__low2half(p), __high2half(p)));
        if (q & 1) s1 += pf; else s0 += pf;
    }
    float s = s0 + s1;
    #pragma unroll
    for (int o = 16; o > 0; o >>= 1) s += __shfl_xor_sync(0xffffffffu, s, o);

    __shared__ float sM[2][4], sS[2][4];
    if (lane == 0) { sM[rloc][quarter] = m; sS[rloc][quarter] = s; }
    __syncthreads();
    if (t < 2) {
        float M2 = sM[t][0];
        #pragma unroll
        for (int w = 1; w < 4; w++) M2 = fmaxf(M2, sM[t][w]);
        float S2 = 0.f;
        #pragma unroll
        for (int w = 0; w < 4; w++) S2 += sS[t][w] * exp2f(sM[t][w] - M2);
        float L = M2 + __log2f(S2);
        const int r = blockIdx.x * 2 + t;
        g_vbh[r] = __float2half(g_lb2[r] - L);
        g_Lg2[r] = L;
    }
}

__global__ void final_kernel(const float* __restrict__ h, const float* __restrict__ hi,
                             float* __restrict__ out) {
    const int t = threadIdx.x;
    double acc = 0.0;
    for (int i = t; i < Nn; i += 256)
        acc += (double)h[i] * (LN2 * (double)g_L2f[i] - (double)g_off[i] - 0.5 * (double)g_la[i]);
    for (int j = t; j < Mm; j += 256)
        acc += (double)hi[j] * (LN2 * (double)g_Lg2[j] - 0.5 * (double)g_lb[j]);
    __shared__ double sd[256];
    sd[t] = acc; __syncthreads();
    for (int o = 128; o > 0; o >>= 1) { if (t < o) sd[t] += sd[t + o]; __syncthreads(); }
    if (t == 0) out[0] = (float)exp(EPS_D * sd[0]);
}

extern "C" void kernel_launch(void* const* d_in, const int* in_sizes, int n_in,
                              void* d_out, int out_size) {
    const float *dp = nullptr, *sip = nullptr, *hp = nullptr, *hip = nullptr, *Wp = nullptr;
    for (int i = 0; i < n_in; i++) {
        switch (in_sizes[i]) {
            case Nn * Dd: dp  = (const float*)d_in[i]; break;
            case Mm * Dd: sip = (const float*)d_in[i]; break;
            case Nn:      hp  = (const float*)d_in[i]; break;
            case Mm:      hip = (const float*)d_in[i]; break;
            case Dd * Dd: Wp  = (const float*)d_in[i]; break;
        }
    }
    if (!dp)  dp  = (const float*)d_in[0];
    if (!sip) sip = (const float*)d_in[1];
    if (!hp)  hp  = (const float*)d_in[2];
    if (!hip) hip = (const float*)d_in[3];
    if (!Wp)  Wp  = (const float*)d_in[4];

    float* gX; cudaGetSymbolAddress((void**)&gX, g_X);
    float* gY; cudaGetSymbolAddress((void**)&gY, g_Y);

    prep_kernel<<<(Nn + 255) / 256, 256>>>(hp, hip);
    tf32_gemm<0><<<dim3(Dd / 64, Nn / 128), 256>>>(dp, Wp, gX, Dd);
    tf32_gemm<0><<<dim3(Dd / 64, Mm / 128), 256>>>(sip, Wp, gY, Dd);
    rownorm_kernel<0><<<Nn, 256>>>();
    rownorm_kernel<1><<<Mm, 256>>>();
    nybar_kernel<<<1, 256>>>();
    off_kernel<<<(Nn + 255) / 256, 256>>>();
    tf32_gemm<1><<<dim3(Mm / 64, Nn / 128), 256>>>(gX, gY, nullptr, 0);

    for (int it = 0; it < 50; it++) {
        softminA<0><<<Nn / 8, 256>>>();
        softminB<<<Mm / 2, 256>>>();
    }
    softminA<1><<<Nn / 8, 256>>>();

    final_kernel<<<1, 256>>>(hp, hip, (float*)d_out);
}